// round 12
// baseline (speedup 1.0000x reference)
#include <cuda_runtime.h>
#include <cuda_bf16.h>
#include <cstdint>

// dynFilter: out[b,1,h,w] = tanh( sum_{c,ky,kx} x[b,c,h+ky-2,w+kx-2] * filt[b, c*25+ky*5+kx, h, w] )
// x [8,4,256,256] f32, filt [8,100,256,256] f32, out [8,1,256,256] f32.
// 210 MB compulsory one-pass stream. LDG kernels plateau at ~73% DRAM because
// per-warp MLP is register-bound (R7: deeper reg pipeline spills; R11: L2
// pinning across replays is a no-op).
// R12: cp.async (LDGSTS) filt stream into a per-thread-private 8-deep smem
// FIFO: 8 loads in flight per thread at ZERO register cost, scoreboarded by
// commit/wait groups, no barriers (each thread consumes only its own 16B).
// Prologue cp.async batch overlaps the x smem fill for free.

#define KK 5
#define PADK 2
#define CC 4
#define HH 256
#define WW 256
#define TILE_H 4
#define TILE_W 128
#define NROWS (TILE_H + 2 * PADK)        // 8 halo rows
#define NCOLS (TILE_W + 2 * PADK)        // 132 halo cols
#define NCOLS_PAD 136                    // 16B-aligned row stride
#define NP (CC * KK * KK)                // 100 filt planes
#define DQ 8                             // cp.async ring depth (planes)

__device__ __forceinline__ float tanh_approx(float v) {
    float r;
    asm("tanh.approx.f32 %0, %1;" : "=f"(r) : "f"(v));
    return r;
}

__device__ __forceinline__ void cpa16(uint32_t saddr, const void* gaddr) {
    asm volatile("cp.async.cg.shared.global [%0], [%1], 16;"
                 :: "r"(saddr), "l"(gaddr));
}
#define CPA_COMMIT() asm volatile("cp.async.commit_group;")
#define CPA_WAIT(n)  asm volatile("cp.async.wait_group %0;" :: "n"(n))

__global__ __launch_bounds__(128, 6)
void dynfilter_kernel(const float* __restrict__ x,
                      const float* __restrict__ filt,
                      float* __restrict__ out)
{
    const int b     = blockIdx.z;
    const int whalf = blockIdx.y;            // 0..1
    const int h0    = blockIdx.x * TILE_H;   // tile row base
    const int w0    = whalf * TILE_W;        // tile col base
    const int tid   = threadIdx.x;

    const int hr = tid >> 5;       // 0..3 row within tile
    const int q  = tid & 31;       // 0..31 float4 column within tile
    const int h  = h0 + hr;
    const int wl = q << 2;         // local smem col of window start (w-2 incl halo)

    __shared__ __align__(16) float  xs[CC][NROWS][NCOLS_PAD];   // 17408 B
    __shared__ __align__(16) float4 ring[DQ][128];              // 16384 B

    const long plane = (long)(HH * WW / 4);  // 16384 float4 per plane
    const float4* __restrict__ fp =
        (const float4*)filt +
        (((long)b * (CC * KK * KK) * HH + h) * (WW / 4) + (whalf * 32 + q));

    const uint32_t rb =
        (uint32_t)__cvta_generic_to_shared(&ring[0][0]) + (uint32_t)tid * 16u;

    // ---- Prime the FIFO: planes 0..DQ-1 (issued before the x fill so the
    //      fill + barrier run entirely under their DRAM latency) ----
    #pragma unroll
    for (int p = 0; p < DQ; ++p) {
        cpa16(rb + (uint32_t)p * 2048u, fp + (long)p * plane);
        CPA_COMMIT();
    }

    // Cooperative halo load of x: rows h0-2..h0+5, cols w0-2..w0+129.
    #pragma unroll
    for (int it = 0; it < (CC * NROWS * NCOLS + 127) / 128; ++it) {
        int idx = it * 128 + tid;
        if (idx < CC * NROWS * NCOLS) {
            int c   = idx / (NROWS * NCOLS);
            int rem = idx % (NROWS * NCOLS);
            int r   = rem / NCOLS;
            int col = rem % NCOLS;
            int gr = h0 - PADK + r;
            int gc = w0 - PADK + col;
            float v = 0.0f;
            if (gr >= 0 && gr < HH && gc >= 0 && gc < WW)
                v = x[(((b * CC) + c) * HH + gr) * WW + gc];
            xs[c][r][col] = v;
        }
    }
    __syncthreads();

    float acc0 = 0.f, acc1 = 0.f, acc2 = 0.f, acc3 = 0.f;

    #pragma unroll
    for (int c = 0; c < CC; ++c) {
        #pragma unroll
        for (int ky = 0; ky < KK; ++ky) {
            // 8-float window row via two conflict-free LDS.128.
            const float4 a  = *(const float4*)&xs[c][hr + ky][wl];
            const float4 bb = *(const float4*)&xs[c][hr + ky][wl + 4];
            const float xr0 = a.x,  xr1 = a.y,  xr2 = a.z,  xr3 = a.w;
            const float xr4 = bb.x, xr5 = bb.y, xr6 = bb.z, xr7 = bb.w;
            const float xrr[8] = {xr0, xr1, xr2, xr3, xr4, xr5, xr6, xr7};

            #pragma unroll
            for (int kx = 0; kx < KK; ++kx) {
                const int p = (c * KK + ky) * KK + kx;

                // Ensure plane p's group has landed (committed = DQ + p so far;
                // <= DQ-1 pending  =>  planes 0..p complete).
                CPA_WAIT(DQ - 1);
                const float4 f = ring[p % DQ][tid];

                acc0 = fmaf(xrr[kx + 0], f.x, acc0);
                acc1 = fmaf(xrr[kx + 1], f.y, acc1);
                acc2 = fmaf(xrr[kx + 2], f.z, acc2);
                acc3 = fmaf(xrr[kx + 3], f.w, acc3);

                // Refill the slot just consumed with plane p+DQ (the LDGSTS
                // smem write lands >=234cyc after issue, long after the LDS
                // above has read the slot). Empty commit keeps group counting
                // uniform in the tail.
                if (p + DQ < NP)
                    cpa16(rb + (uint32_t)(p % DQ) * 2048u, fp + (long)(p + DQ) * plane);
                CPA_COMMIT();
            }
        }
    }

    float4 o;
    o.x = tanh_approx(acc0);
    o.y = tanh_approx(acc1);
    o.z = tanh_approx(acc2);
    o.w = tanh_approx(acc3);
    ((float4*)out)[((long)b * HH + h) * (WW / 4) + whalf * 32 + q] = o;
}

extern "C" void kernel_launch(void* const* d_in, const int* in_sizes, int n_in,
                              void* d_out, int out_size)
{
    const float* x    = (const float*)d_in[0];   // [8,4,256,256]
    const float* filt = (const float*)d_in[1];   // [8,100,256,256]
    float* out        = (float*)d_out;           // [8,1,256,256]

    dim3 grid(HH / TILE_H, WW / TILE_W, 8);   // 64 x 2 x 8 = 1024 CTAs
    dim3 block(128);
    dynfilter_kernel<<<grid, block>>>(x, filt, out);
}